// round 14
// baseline (speedup 1.0000x reference)
#include <cuda_runtime.h>
#include <math.h>
#include <stdint.h>

#define B_   8
#define LQ_  2048
#define LK_  2048
#define HID_ 1024

// smem strides (floats): k-major tiles [row][k] stride 20; n-major [k][n] stride 136.
#define SK 20
#define SN 136

// tf32-rounded scratch copies (rna applied once; GEMMs then load raw bits)
__device__ unsigned g_Qt[(size_t)B_ * LQ_ * HID_];   // 64MB
__device__ unsigned g_Kt[(size_t)B_ * LK_ * HID_];   // 64MB
__device__ unsigned g_At[(size_t)B_ * LQ_ * LK_];    // 128MB

__device__ __forceinline__ unsigned f2tf(float x) {
    unsigned u;
    asm("cvt.rna.tf32.f32 %0, %1;" : "=r"(u) : "f"(x));
    return u;
}

__device__ __forceinline__ void mma_tf32(float* d, const unsigned* a, const unsigned* b) {
    asm volatile(
        "mma.sync.aligned.m16n8k8.row.col.f32.tf32.tf32.f32 "
        "{%0,%1,%2,%3}, {%4,%5,%6,%7}, {%8,%9}, {%0,%1,%2,%3};\n"
        : "+f"(d[0]), "+f"(d[1]), "+f"(d[2]), "+f"(d[3])
        : "r"(a[0]), "r"(a[1]), "r"(a[2]), "r"(a[3]),
          "r"(b[0]), "r"(b[1]));
}

__device__ __forceinline__ void cp_async16(uint32_t smem_addr, const void* gptr) {
    asm volatile("cp.async.cg.shared.global [%0], [%1], 16;"
                 :: "r"(smem_addr), "l"(gptr));
}
#define CP_COMMIT() asm volatile("cp.async.commit_group;" ::: "memory")
#define CP_WAIT2()  asm volatile("cp.async.wait_group 2;" ::: "memory")

// ---------------------------------------------------------------------------
// Kernel 0: elementwise rna-round to tf32 bits (Q and K in one launch)
// ---------------------------------------------------------------------------
__global__ __launch_bounds__(256)
void k0_round(const float* __restrict__ q, const float* __restrict__ k,
              unsigned* __restrict__ qt, unsigned* __restrict__ kt, int n4)
{
    const int i = blockIdx.x * 256 + threadIdx.x;
    if (i < n4) {
        float4 v = ((const float4*)q)[i];
        ((uint4*)qt)[i] = make_uint4(f2tf(v.x), f2tf(v.y), f2tf(v.z), f2tf(v.w));
        float4 w = ((const float4*)k)[i];
        ((uint4*)kt)[i] = make_uint4(f2tf(w.x), f2tf(w.y), f2tf(w.z), f2tf(w.w));
    }
}

// ---------------------------------------------------------------------------
// Kernel 1: P = exp( (Qt.Kt^T / 32) * mask )  (unnormalized; k2 normalizes)
// CTA 128x128, BK=16, 256 threads = 8 warps (2M x 4N), warp tile 64x32.
// 4-stage cp.async ring, one barrier per iter, per-half fragment loads.
// 2 CTAs/SM -> 16 warps/SM (4/SMSP) for latency hiding.
// ---------------------------------------------------------------------------
__global__ __launch_bounds__(256, 2)
void k1_qk_exp(const unsigned* __restrict__ Q, const unsigned* __restrict__ Kf,
               const float* __restrict__ mask, float* __restrict__ P)
{
    extern __shared__ unsigned sm[];
    unsigned* sA[4] = { sm, sm + 2560, sm + 2 * 2560, sm + 3 * 2560 };
    unsigned* sB[4] = { sm + 4 * 2560, sm + 5 * 2560, sm + 6 * 2560, sm + 7 * 2560 };

    const int b  = blockIdx.z;
    const int m0 = blockIdx.y * 128;
    const int n0 = blockIdx.x * 128;

    const unsigned* Qb = Q  + (size_t)b * LQ_ * HID_;
    const unsigned* Kb = Kf + (size_t)b * LK_ * HID_;

    const int tid  = threadIdx.x;
    const int wid  = tid >> 5;
    const int lane = tid & 31;
    const int qid  = lane >> 2;
    const int rid  = lane & 3;
    const int wm   = (wid & 1) * 64;    // 2 M warps
    const int wn   = (wid >> 1) * 32;   // 4 N warps

    const int lrow = tid >> 2;          // 0..63
    const int lkq  = (tid & 3) << 2;    // 0,4,8,12

    uint32_t sAa[4], sBa[4];
#pragma unroll
    for (int u = 0; u < 4; u++) {
        sAa[u] = (uint32_t)__cvta_generic_to_shared(sA[u]);
        sBa[u] = (uint32_t)__cvta_generic_to_shared(sB[u]);
    }

    float acc[4][4][4];
#pragma unroll
    for (int i = 0; i < 4; i++)
#pragma unroll
        for (int j = 0; j < 4; j++)
#pragma unroll
            for (int c = 0; c < 4; c++) acc[i][j][c] = 0.0f;

    auto fill = [&](int stage, int buf) {
        const int kk = stage * 16;
#pragma unroll
        for (int j = 0; j < 2; j++) {
            const int row = lrow + j * 64;
            cp_async16(sAa[buf] + (row * SK + lkq) * 4,
                       Qb + (size_t)(m0 + row) * HID_ + kk + lkq);
            cp_async16(sBa[buf] + (row * SK + lkq) * 4,
                       Kb + (size_t)(n0 + row) * HID_ + kk + lkq);
        }
    };

    fill(0, 0); CP_COMMIT();
    fill(1, 1); CP_COMMIT();
    fill(2, 2); CP_COMMIT();

    const int NIT = HID_ / 16;
    int cur = 0;
    for (int it = 0; it < NIT; it++) {
        CP_WAIT2();
        __syncthreads();
        if (it + 3 < NIT) fill(it + 3, (it + 3) & 3);
        CP_COMMIT();
        const unsigned* cA = sA[cur];
        const unsigned* cB = sB[cur];
        cur = (cur + 1) & 3;

#pragma unroll
        for (int h = 0; h < 2; h++) {
            const int ks = h * 8;
            unsigned af[4][4];
#pragma unroll
            for (int mt = 0; mt < 4; mt++) {
                const int r = wm + mt * 16 + qid;
                af[mt][0] = cA[r * SK + ks + rid];
                af[mt][1] = cA[(r + 8) * SK + ks + rid];
                af[mt][2] = cA[r * SK + ks + 4 + rid];
                af[mt][3] = cA[(r + 8) * SK + ks + 4 + rid];
            }
            unsigned bf[4][2];
#pragma unroll
            for (int nt = 0; nt < 4; nt++) {
                const int c = wn + nt * 8 + qid;
                bf[nt][0] = cB[c * SK + ks + rid];
                bf[nt][1] = cB[c * SK + ks + 4 + rid];
            }
#pragma unroll
            for (int mt = 0; mt < 4; mt++)
#pragma unroll
                for (int nt = 0; nt < 4; nt++)
                    mma_tf32(acc[mt][nt], af[mt], bf[nt]);
        }
    }

    const float s = 0.03125f;
#pragma unroll
    for (int mt = 0; mt < 4; mt++) {
#pragma unroll
        for (int nt = 0; nt < 4; nt++) {
            const int r = m0 + wm + mt * 16 + qid;
            const int c = n0 + wn + nt * 8 + 2 * rid;
            const size_t i0 = ((size_t)b * LQ_ + r) * LK_ + c;
            const size_t i1 = ((size_t)b * LQ_ + r + 8) * LK_ + c;
            float2 ma = *(const float2*)(mask + i0);
            float2 mb = *(const float2*)(mask + i1);
            float2 o0, o1;
            o0.x = __expf(acc[mt][nt][0] * s * ma.x);
            o0.y = __expf(acc[mt][nt][1] * s * ma.y);
            o1.x = __expf(acc[mt][nt][2] * s * mb.x);
            o1.y = __expf(acc[mt][nt][3] * s * mb.y);
            *(float2*)(P + i0) = o0;
            *(float2*)(P + i1) = o1;
        }
    }
}

// ---------------------------------------------------------------------------
// Kernel 2: per-row normalization; also emit rna-rounded tf32 copy to g_At
// ---------------------------------------------------------------------------
__global__ __launch_bounds__(256)
void k2_norm(float* __restrict__ P, unsigned* __restrict__ Pt)
{
    __shared__ float red[256];
    float*    prow = P  + (size_t)blockIdx.x * LK_;
    unsigned* trow = Pt + (size_t)blockIdx.x * LK_;
    const int tid = threadIdx.x;

    float4 v0 = ((const float4*)prow)[tid];
    float4 v1 = ((const float4*)prow)[tid + 256];
    float s = v0.x + v0.y + v0.z + v0.w + v1.x + v1.y + v1.z + v1.w;
    red[tid] = s;
    __syncthreads();
#pragma unroll
    for (int off = 128; off > 0; off >>= 1) {
        if (tid < off) red[tid] += red[tid + off];
        __syncthreads();
    }
    const float inv = 1.0f / red[0];
    v0.x *= inv; v0.y *= inv; v0.z *= inv; v0.w *= inv;
    v1.x *= inv; v1.y *= inv; v1.z *= inv; v1.w *= inv;
    ((float4*)prow)[tid]       = v0;
    ((float4*)prow)[tid + 256] = v1;
    ((uint4*)trow)[tid] =
        make_uint4(f2tf(v0.x), f2tf(v0.y), f2tf(v0.z), f2tf(v0.w));
    ((uint4*)trow)[tid + 256] =
        make_uint4(f2tf(v1.x), f2tf(v1.y), f2tf(v1.z), f2tf(v1.w));
}

// ---------------------------------------------------------------------------
// Kernel 3: context = attn_t . Kt
// A [row][k] stride SK; B [k][n] stride SN. Same 8-warp 64x32 structure.
// ---------------------------------------------------------------------------
__global__ __launch_bounds__(256, 2)
void k3_av(const unsigned* __restrict__ A, const unsigned* __restrict__ Kf,
           float* __restrict__ C)
{
    extern __shared__ unsigned sm[];
    unsigned* sA[4] = { sm, sm + 2560, sm + 2 * 2560, sm + 3 * 2560 };
    unsigned* sB[4] = { sm + 4 * 2560,
                        sm + 4 * 2560 + 16 * SN,
                        sm + 4 * 2560 + 32 * SN,
                        sm + 4 * 2560 + 48 * SN };

    const int b  = blockIdx.z;
    const int m0 = blockIdx.y * 128;
    const int n0 = blockIdx.x * 128;

    const unsigned* Ab = A  + (size_t)b * LQ_ * LK_;
    const unsigned* Kb = Kf + (size_t)b * LK_ * HID_;

    const int tid  = threadIdx.x;
    const int wid  = tid >> 5;
    const int lane = tid & 31;
    const int qid  = lane >> 2;
    const int rid  = lane & 3;
    const int wm   = (wid & 1) * 64;
    const int wn   = (wid >> 1) * 32;

    const int lrow = tid >> 2;          // 0..63
    const int lkq  = (tid & 3) << 2;
    const int lkr  = tid >> 5;          // 0..7
    const int lnc  = (tid & 31) << 2;   // 0..124

    uint32_t sAa[4], sBa[4];
#pragma unroll
    for (int u = 0; u < 4; u++) {
        sAa[u] = (uint32_t)__cvta_generic_to_shared(sA[u]);
        sBa[u] = (uint32_t)__cvta_generic_to_shared(sB[u]);
    }

    float acc[4][4][4];
#pragma unroll
    for (int i = 0; i < 4; i++)
#pragma unroll
        for (int j = 0; j < 4; j++)
#pragma unroll
            for (int c = 0; c < 4; c++) acc[i][j][c] = 0.0f;

    auto fill = [&](int stage, int buf) {
        const int kk = stage * 16;
#pragma unroll
        for (int j = 0; j < 2; j++) {
            const int row = lrow + j * 64;
            cp_async16(sAa[buf] + (row * SK + lkq) * 4,
                       Ab + (size_t)(m0 + row) * LK_ + kk + lkq);
            const int kr = lkr + j * 8;
            cp_async16(sBa[buf] + (kr * SN + lnc) * 4,
                       Kb + (size_t)(kk + kr) * HID_ + n0 + lnc);
        }
    };

    fill(0, 0); CP_COMMIT();
    fill(1, 1); CP_COMMIT();
    fill(2, 2); CP_COMMIT();

    const int NIT = LK_ / 16;
    int cur = 0;
    for (int it = 0; it < NIT; it++) {
        CP_WAIT2();
        __syncthreads();
        if (it + 3 < NIT) fill(it + 3, (it + 3) & 3);
        CP_COMMIT();
        const unsigned* cA = sA[cur];
        const unsigned* cB = sB[cur];
        cur = (cur + 1) & 3;

#pragma unroll
        for (int h = 0; h < 2; h++) {
            const int ks = h * 8;
            unsigned af[4][4];
#pragma unroll
            for (int mt = 0; mt < 4; mt++) {
                const int r = wm + mt * 16 + qid;
                af[mt][0] = cA[r * SK + ks + rid];
                af[mt][1] = cA[(r + 8) * SK + ks + rid];
                af[mt][2] = cA[r * SK + ks + 4 + rid];
                af[mt][3] = cA[(r + 8) * SK + ks + 4 + rid];
            }
            unsigned bf[4][2];
#pragma unroll
            for (int nt = 0; nt < 4; nt++) {
                const int c = wn + nt * 8 + qid;
                bf[nt][0] = cB[(ks + rid) * SN + c];
                bf[nt][1] = cB[(ks + 4 + rid) * SN + c];
            }
#pragma unroll
            for (int mt = 0; mt < 4; mt++)
#pragma unroll
                for (int nt = 0; nt < 4; nt++)
                    mma_tf32(acc[mt][nt], af[mt], bf[nt]);
        }
    }

#pragma unroll
    for (int mt = 0; mt < 4; mt++) {
#pragma unroll
        for (int nt = 0; nt < 4; nt++) {
            const int r = m0 + wm + mt * 16 + qid;
            const int c = n0 + wn + nt * 8 + 2 * rid;
            const size_t i0 = ((size_t)b * LQ_ + r) * HID_ + c;
            const size_t i1 = ((size_t)b * LQ_ + r + 8) * HID_ + c;
            *(float2*)(C + i0) = make_float2(acc[mt][nt][0], acc[mt][nt][1]);
            *(float2*)(C + i1) = make_float2(acc[mt][nt][2], acc[mt][nt][3]);
        }
    }
}

// ---------------------------------------------------------------------------
extern "C" void kernel_launch(void* const* d_in, const int* in_sizes, int n_in,
                              void* d_out, int out_size)
{
    const float* Q    = (const float*)d_in[0];
    const float* Kf   = (const float*)d_in[1];
    const float* mask = (const float*)d_in[2];

    float* ctx  = (float*)d_out;                      // [B, LQ, HID]
    float* attn = ctx + (size_t)B_ * LQ_ * HID_;      // [B, LQ, LK]

    void *qt = 0, *kt = 0, *at = 0;
    cudaGetSymbolAddress(&qt, g_Qt);
    cudaGetSymbolAddress(&kt, g_Kt);
    cudaGetSymbolAddress(&at, g_At);

    const int smem1 = 8 * 2560 * 4;                        // 81920 B
    const int smem3 = (4 * 2560 + 4 * 16 * SN) * 4;        // 75776 B

    static bool attr_set = false;
    if (!attr_set) {
        cudaFuncSetAttribute(k1_qk_exp, cudaFuncAttributeMaxDynamicSharedMemorySize, smem1);
        cudaFuncSetAttribute(k3_av,     cudaFuncAttributeMaxDynamicSharedMemorySize, smem3);
        attr_set = true;
    }

    const int n4 = (B_ * LQ_ * HID_) / 4;
    k0_round<<<(n4 + 255) / 256, 256>>>(Q, Kf, (unsigned*)qt, (unsigned*)kt, n4);

    dim3 g1(LK_ / 128, LQ_ / 128, B_);
    k1_qk_exp<<<g1, 256, smem1>>>((const unsigned*)qt, (const unsigned*)kt, mask, attn);

    k2_norm<<<B_ * LQ_, 256>>>(attn, (unsigned*)at);

    dim3 g3(HID_ / 128, LQ_ / 128, B_);
    k3_av<<<g3, 256, smem3>>>((const unsigned*)at, (const unsigned*)kt, ctx);
}

// round 15
// speedup vs baseline: 1.1732x; 1.1732x over previous
#include <cuda_runtime.h>
#include <math.h>
#include <stdint.h>

#define B_   8
#define LQ_  2048
#define LK_  2048
#define HID_ 1024

// smem strides (floats): k-major tiles [row][k] stride 20; n-major [k][n] stride 136.
#define SK 20
#define SN 136

// tf32-rounded scratch (rna applied once; GEMMs then load raw bits)
__device__ unsigned g_Qt[(size_t)B_ * LQ_ * HID_];   // Q, rna tf32
__device__ unsigned g_Kt[(size_t)B_ * LK_ * HID_];   // K, rna tf32
__device__ unsigned g_At[(size_t)B_ * LQ_ * LK_];    // UNNORMALIZED exp(P), rna tf32
__device__ float    g_S [(size_t)B_ * LQ_];          // per-row 1/sum

__device__ __forceinline__ unsigned f2tf(float x) {
    unsigned u;
    asm("cvt.rna.tf32.f32 %0, %1;" : "=r"(u) : "f"(x));
    return u;
}

__device__ __forceinline__ void mma_tf32(float* d, const unsigned* a, const unsigned* b) {
    asm volatile(
        "mma.sync.aligned.m16n8k8.row.col.f32.tf32.tf32.f32 "
        "{%0,%1,%2,%3}, {%4,%5,%6,%7}, {%8,%9}, {%0,%1,%2,%3};\n"
        : "+f"(d[0]), "+f"(d[1]), "+f"(d[2]), "+f"(d[3])
        : "r"(a[0]), "r"(a[1]), "r"(a[2]), "r"(a[3]),
          "r"(b[0]), "r"(b[1]));
}

__device__ __forceinline__ void cp_async16(uint32_t smem_addr, const void* gptr) {
    asm volatile("cp.async.cg.shared.global [%0], [%1], 16;"
                 :: "r"(smem_addr), "l"(gptr));
}
#define CP_COMMIT() asm volatile("cp.async.commit_group;" ::: "memory")
#define CP_WAIT2()  asm volatile("cp.async.wait_group 2;" ::: "memory")

// ---------------------------------------------------------------------------
// Kernel 0: elementwise rna-round to tf32 bits (Q and K in one launch)
// ---------------------------------------------------------------------------
__global__ __launch_bounds__(256)
void k0_round(const float* __restrict__ q, const float* __restrict__ k,
              unsigned* __restrict__ qt, unsigned* __restrict__ kt, int n4)
{
    const int i = blockIdx.x * 256 + threadIdx.x;
    if (i < n4) {
        float4 v = ((const float4*)q)[i];
        ((uint4*)qt)[i] = make_uint4(f2tf(v.x), f2tf(v.y), f2tf(v.z), f2tf(v.w));
        float4 w = ((const float4*)k)[i];
        ((uint4*)kt)[i] = make_uint4(f2tf(w.x), f2tf(w.y), f2tf(w.z), f2tf(w.w));
    }
}

// ---------------------------------------------------------------------------
// Kernel 1: g_At = rna_tf32( exp( (Qt.Kt^T / 32) * mask ) )   (UNNORMALIZED)
// CTA 128x128, BK=16, 4 warps (2Mx2N), warp tile 64x64, 4-stage cp.async ring,
// one barrier per iter. (= round-10 mainloop, epilogue stores tf32 bits)
// ---------------------------------------------------------------------------
__global__ __launch_bounds__(128, 2)
void k1_qk_exp(const unsigned* __restrict__ Q, const unsigned* __restrict__ Kf,
               const float* __restrict__ mask, unsigned* __restrict__ At)
{
    extern __shared__ unsigned sm[];
    unsigned* sA[4] = { sm, sm + 2560, sm + 2 * 2560, sm + 3 * 2560 };
    unsigned* sB[4] = { sm + 4 * 2560, sm + 5 * 2560, sm + 6 * 2560, sm + 7 * 2560 };

    const int b  = blockIdx.z;
    const int m0 = blockIdx.y * 128;
    const int n0 = blockIdx.x * 128;

    const unsigned* Qb = Q  + (size_t)b * LQ_ * HID_;
    const unsigned* Kb = Kf + (size_t)b * LK_ * HID_;

    const int tid  = threadIdx.x;
    const int wid  = tid >> 5;
    const int lane = tid & 31;
    const int qid  = lane >> 2;
    const int rid  = lane & 3;
    const int wm   = (wid & 1) * 64;
    const int wn   = (wid >> 1) * 64;

    const int lrow = tid >> 2;          // 0..31
    const int lkq  = (tid & 3) << 2;    // 0,4,8,12

    uint32_t sAa[4], sBa[4];
#pragma unroll
    for (int u = 0; u < 4; u++) {
        sAa[u] = (uint32_t)__cvta_generic_to_shared(sA[u]);
        sBa[u] = (uint32_t)__cvta_generic_to_shared(sB[u]);
    }

    float acc[4][8][4];
#pragma unroll
    for (int i = 0; i < 4; i++)
#pragma unroll
        for (int j = 0; j < 8; j++)
#pragma unroll
            for (int c = 0; c < 4; c++) acc[i][j][c] = 0.0f;

    auto fill = [&](int stage, int buf) {
        const int kk = stage * 16;
#pragma unroll
        for (int j = 0; j < 4; j++) {
            const int row = lrow + j * 32;
            cp_async16(sAa[buf] + (row * SK + lkq) * 4,
                       Qb + (size_t)(m0 + row) * HID_ + kk + lkq);
            cp_async16(sBa[buf] + (row * SK + lkq) * 4,
                       Kb + (size_t)(n0 + row) * HID_ + kk + lkq);
        }
    };

    fill(0, 0); CP_COMMIT();
    fill(1, 1); CP_COMMIT();
    fill(2, 2); CP_COMMIT();

    const int NIT = HID_ / 16;
    int cur = 0;
    for (int it = 0; it < NIT; it++) {
        CP_WAIT2();
        __syncthreads();
        if (it + 3 < NIT) fill(it + 3, (it + 3) & 3);
        CP_COMMIT();
        const unsigned* cA = sA[cur];
        const unsigned* cB = sB[cur];
        cur = (cur + 1) & 3;

#pragma unroll
        for (int h = 0; h < 2; h++) {
            const int ks = h * 8;
            unsigned af[4][4];
#pragma unroll
            for (int mt = 0; mt < 4; mt++) {
                const int r = wm + mt * 16 + qid;
                af[mt][0] = cA[r * SK + ks + rid];
                af[mt][1] = cA[(r + 8) * SK + ks + rid];
                af[mt][2] = cA[r * SK + ks + 4 + rid];
                af[mt][3] = cA[(r + 8) * SK + ks + 4 + rid];
            }
            unsigned bf[8][2];
#pragma unroll
            for (int nt = 0; nt < 8; nt++) {
                const int c = wn + nt * 8 + qid;
                bf[nt][0] = cB[c * SK + ks + rid];
                bf[nt][1] = cB[c * SK + ks + 4 + rid];
            }
#pragma unroll
            for (int mt = 0; mt < 4; mt++)
#pragma unroll
                for (int nt = 0; nt < 8; nt++)
                    mma_tf32(acc[mt][nt], af[mt], bf[nt]);
        }
    }

    // epilogue: scale, mask-multiply, exp, rna->tf32, store bits (unnormalized)
    const float s = 0.03125f;
#pragma unroll
    for (int mt = 0; mt < 4; mt++) {
#pragma unroll
        for (int nt = 0; nt < 8; nt++) {
            const int r = m0 + wm + mt * 16 + qid;
            const int c = n0 + wn + nt * 8 + 2 * rid;
            const size_t i0 = ((size_t)b * LQ_ + r) * LK_ + c;
            const size_t i1 = ((size_t)b * LQ_ + r + 8) * LK_ + c;
            float2 ma = *(const float2*)(mask + i0);
            float2 mb = *(const float2*)(mask + i1);
            uint2 o0, o1;
            o0.x = f2tf(__expf(acc[mt][nt][0] * s * ma.x));
            o0.y = f2tf(__expf(acc[mt][nt][1] * s * ma.y));
            o1.x = f2tf(__expf(acc[mt][nt][2] * s * mb.x));
            o1.y = f2tf(__expf(acc[mt][nt][3] * s * mb.y));
            *(uint2*)(At + i0) = o0;
            *(uint2*)(At + i1) = o1;
        }
    }
}

// ---------------------------------------------------------------------------
// Kernel 2: read unnormalized tf32 P bits; reduce row sum; write normalized
// f32 attn output and invS[row]. (2 big streams instead of 3)
// ---------------------------------------------------------------------------
__global__ __launch_bounds__(256)
void k2_norm(const unsigned* __restrict__ At, float* __restrict__ attn,
             float* __restrict__ invS)
{
    __shared__ float red[256];
    const unsigned* arow = At   + (size_t)blockIdx.x * LK_;
    float*          orow = attn + (size_t)blockIdx.x * LK_;
    const int tid = threadIdx.x;

    uint4 u0 = ((const uint4*)arow)[tid];
    uint4 u1 = ((const uint4*)arow)[tid + 256];
    float4 v0 = make_float4(__uint_as_float(u0.x), __uint_as_float(u0.y),
                            __uint_as_float(u0.z), __uint_as_float(u0.w));
    float4 v1 = make_float4(__uint_as_float(u1.x), __uint_as_float(u1.y),
                            __uint_as_float(u1.z), __uint_as_float(u1.w));
    float s = v0.x + v0.y + v0.z + v0.w + v1.x + v1.y + v1.z + v1.w;
    red[tid] = s;
    __syncthreads();
#pragma unroll
    for (int off = 128; off > 0; off >>= 1) {
        if (tid < off) red[tid] += red[tid + off];
        __syncthreads();
    }
    const float inv = 1.0f / red[0];
    v0.x *= inv; v0.y *= inv; v0.z *= inv; v0.w *= inv;
    v1.x *= inv; v1.y *= inv; v1.z *= inv; v1.w *= inv;
    ((float4*)orow)[tid]       = v0;
    ((float4*)orow)[tid + 256] = v1;
    if (tid == 0) invS[blockIdx.x] = inv;
}

// ---------------------------------------------------------------------------
// Kernel 3: context = (invS * At_unnorm) . Kt  — scale applied in epilogue.
// A [row][k] stride SK; B [k][n] stride SN. (= round-10 mainloop)
// ---------------------------------------------------------------------------
__global__ __launch_bounds__(128, 2)
void k3_av(const unsigned* __restrict__ A, const unsigned* __restrict__ Kf,
           const float* __restrict__ invS, float* __restrict__ C)
{
    extern __shared__ unsigned sm[];
    unsigned* sA[4] = { sm, sm + 2560, sm + 2 * 2560, sm + 3 * 2560 };
    unsigned* sB[4] = { sm + 4 * 2560,
                        sm + 4 * 2560 + 16 * SN,
                        sm + 4 * 2560 + 32 * SN,
                        sm + 4 * 2560 + 48 * SN };

    const int b  = blockIdx.z;
    const int m0 = blockIdx.y * 128;
    const int n0 = blockIdx.x * 128;

    const unsigned* Ab = A  + (size_t)b * LQ_ * LK_;
    const unsigned* Kb = Kf + (size_t)b * LK_ * HID_;

    const int tid  = threadIdx.x;
    const int wid  = tid >> 5;
    const int lane = tid & 31;
    const int qid  = lane >> 2;
    const int rid  = lane & 3;
    const int wm   = (wid & 1) * 64;
    const int wn   = (wid >> 1) * 64;

    const int lrow = tid >> 2;
    const int lkq  = (tid & 3) << 2;
    const int lkr  = tid >> 5;          // 0..3
    const int lnc  = (tid & 31) << 2;   // 0..124

    uint32_t sAa[4], sBa[4];
#pragma unroll
    for (int u = 0; u < 4; u++) {
        sAa[u] = (uint32_t)__cvta_generic_to_shared(sA[u]);
        sBa[u] = (uint32_t)__cvta_generic_to_shared(sB[u]);
    }

    float acc[4][8][4];
#pragma unroll
    for (int i = 0; i < 4; i++)
#pragma unroll
        for (int j = 0; j < 8; j++)
#pragma unroll
            for (int c = 0; c < 4; c++) acc[i][j][c] = 0.0f;

    auto fill = [&](int stage, int buf) {
        const int kk = stage * 16;
#pragma unroll
        for (int j = 0; j < 4; j++) {
            const int row = lrow + j * 32;
            cp_async16(sAa[buf] + (row * SK + lkq) * 4,
                       Ab + (size_t)(m0 + row) * LK_ + kk + lkq);
            const int kr = lkr + j * 4;
            cp_async16(sBa[buf] + (kr * SN + lnc) * 4,
                       Kb + (size_t)(kk + kr) * HID_ + n0 + lnc);
        }
    };

    fill(0, 0); CP_COMMIT();
    fill(1, 1); CP_COMMIT();
    fill(2, 2); CP_COMMIT();

    const int NIT = LK_ / 16;
    int cur = 0;
    for (int it = 0; it < NIT; it++) {
        CP_WAIT2();
        __syncthreads();
        if (it + 3 < NIT) fill(it + 3, (it + 3) & 3);
        CP_COMMIT();
        const unsigned* cA = sA[cur];
        const unsigned* cB = sB[cur];
        cur = (cur + 1) & 3;

#pragma unroll
        for (int h = 0; h < 2; h++) {
            const int ks = h * 8;
            unsigned af[4][4];
#pragma unroll
            for (int mt = 0; mt < 4; mt++) {
                const int r = wm + mt * 16 + qid;
                af[mt][0] = cA[r * SK + ks + rid];
                af[mt][1] = cA[(r + 8) * SK + ks + rid];
                af[mt][2] = cA[r * SK + ks + 4 + rid];
                af[mt][3] = cA[(r + 8) * SK + ks + 4 + rid];
            }
            unsigned bf[8][2];
#pragma unroll
            for (int nt = 0; nt < 8; nt++) {
                const int c = wn + nt * 8 + qid;
                bf[nt][0] = cB[(ks + rid) * SN + c];
                bf[nt][1] = cB[(ks + 4 + rid) * SN + c];
            }
#pragma unroll
            for (int mt = 0; mt < 4; mt++)
#pragma unroll
                for (int nt = 0; nt < 8; nt++)
                    mma_tf32(acc[mt][nt], af[mt], bf[nt]);
        }
    }

    // epilogue: scale by invS[row], store f32
#pragma unroll
    for (int mt = 0; mt < 4; mt++) {
        const int r  = m0 + wm + mt * 16 + qid;
        const float is0 = invS[(size_t)b * LQ_ + r];
        const float is1 = invS[(size_t)b * LQ_ + r + 8];
#pragma unroll
        for (int nt = 0; nt < 8; nt++) {
            const int c = n0 + wn + nt * 8 + 2 * rid;
            const size_t i0 = ((size_t)b * LQ_ + r) * HID_ + c;
            const size_t i1 = ((size_t)b * LQ_ + r + 8) * HID_ + c;
            *(float2*)(C + i0) = make_float2(acc[mt][nt][0] * is0, acc[mt][nt][1] * is0);
            *(float2*)(C + i1) = make_float2(acc[mt][nt][2] * is1, acc[mt][nt][3] * is1);
        }
    }
}

// ---------------------------------------------------------------------------
extern "C" void kernel_launch(void* const* d_in, const int* in_sizes, int n_in,
                              void* d_out, int out_size)
{
    const float* Q    = (const float*)d_in[0];
    const float* Kf   = (const float*)d_in[1];
    const float* mask = (const float*)d_in[2];

    float* ctx  = (float*)d_out;                      // [B, LQ, HID]
    float* attn = ctx + (size_t)B_ * LQ_ * HID_;      // [B, LQ, LK]

    void *qt = 0, *kt = 0, *at = 0, *sv = 0;
    cudaGetSymbolAddress(&qt, g_Qt);
    cudaGetSymbolAddress(&kt, g_Kt);
    cudaGetSymbolAddress(&at, g_At);
    cudaGetSymbolAddress(&sv, g_S);

    const int smem1 = 8 * 2560 * 4;                        // 81920 B
    const int smem3 = (4 * 2560 + 4 * 16 * SN) * 4;        // 75776 B

    static bool attr_set = false;
    if (!attr_set) {
        cudaFuncSetAttribute(k1_qk_exp, cudaFuncAttributeMaxDynamicSharedMemorySize, smem1);
        cudaFuncSetAttribute(k3_av,     cudaFuncAttributeMaxDynamicSharedMemorySize, smem3);
        attr_set = true;
    }

    const int n4 = (B_ * LQ_ * HID_) / 4;
    k0_round<<<(n4 + 255) / 256, 256>>>(Q, Kf, (unsigned*)qt, (unsigned*)kt, n4);

    dim3 g1(LK_ / 128, LQ_ / 128, B_);
    k1_qk_exp<<<g1, 128, smem1>>>((const unsigned*)qt, (const unsigned*)kt, mask,
                                  (unsigned*)at);

    k2_norm<<<B_ * LQ_, 256>>>((const unsigned*)at, attn, (float*)sv);

    dim3 g3(HID_ / 128, LQ_ / 128, B_);
    k3_av<<<g3, 128, smem3>>>((const unsigned*)at, (const unsigned*)kt,
                              (const float*)sv, ctx);
}

// round 16
// speedup vs baseline: 1.8505x; 1.5774x over previous
#include <cuda_runtime.h>
#include <cuda_fp16.h>
#include <math.h>
#include <stdint.h>

#define B_   8
#define LQ_  2048
#define LK_  2048
#define HID_ 1024

// smem stride in half2 units: row = 20 half2 (80B). Fragment banks
// (20*qid + rid) mod 32 are fully distinct -> conflict-free.
#define SKH 20

// fp16 scratch (rne applied once; GEMMs load raw halfs)
__device__ __half g_Qh [(size_t)B_ * LQ_ * HID_];   // Q fp16, k-major
__device__ __half g_Kh [(size_t)B_ * LK_ * HID_];   // K fp16, k-major (for k1)
__device__ __half g_KTh[(size_t)B_ * HID_ * LK_];   // K^T fp16 (for k3)
__device__ __half g_Ath[(size_t)B_ * LQ_ * LK_];    // UNNORMALIZED exp(P), fp16
__device__ float  g_S  [(size_t)B_ * LQ_];          // per-row 1/sum

__device__ __forceinline__ unsigned h2u(__half2 h) {
    return *(unsigned*)&h;
}

__device__ __forceinline__ void mma_f16(float* d, const unsigned* a, const unsigned* b) {
    asm volatile(
        "mma.sync.aligned.m16n8k16.row.col.f32.f16.f16.f32 "
        "{%0,%1,%2,%3}, {%4,%5,%6,%7}, {%8,%9}, {%0,%1,%2,%3};\n"
        : "+f"(d[0]), "+f"(d[1]), "+f"(d[2]), "+f"(d[3])
        : "r"(a[0]), "r"(a[1]), "r"(a[2]), "r"(a[3]),
          "r"(b[0]), "r"(b[1]));
}

__device__ __forceinline__ void cp_async16(uint32_t smem_addr, const void* gptr) {
    asm volatile("cp.async.cg.shared.global [%0], [%1], 16;"
                 :: "r"(smem_addr), "l"(gptr));
}
#define CP_COMMIT() asm volatile("cp.async.commit_group;" ::: "memory")
#define CP_WAIT2()  asm volatile("cp.async.wait_group 2;" ::: "memory")

// ---------------------------------------------------------------------------
// Kernel 0: f32 -> fp16 (rne) for Q and K, k-major (8 elems per thread)
// ---------------------------------------------------------------------------
__global__ __launch_bounds__(256)
void k0_round(const float* __restrict__ q, const float* __restrict__ k,
              __half* __restrict__ qh, __half* __restrict__ kh, int n8)
{
    const int i = blockIdx.x * 256 + threadIdx.x;
    if (i < n8) {
        float4 a0 = ((const float4*)q)[2 * i];
        float4 a1 = ((const float4*)q)[2 * i + 1];
        uint4 o;
        o.x = h2u(__floats2half2_rn(a0.x, a0.y));
        o.y = h2u(__floats2half2_rn(a0.z, a0.w));
        o.z = h2u(__floats2half2_rn(a1.x, a1.y));
        o.w = h2u(__floats2half2_rn(a1.z, a1.w));
        ((uint4*)qh)[i] = o;
        float4 b0 = ((const float4*)k)[2 * i];
        float4 b1 = ((const float4*)k)[2 * i + 1];
        uint4 p;
        p.x = h2u(__floats2half2_rn(b0.x, b0.y));
        p.y = h2u(__floats2half2_rn(b0.z, b0.w));
        p.z = h2u(__floats2half2_rn(b1.x, b1.y));
        p.w = h2u(__floats2half2_rn(b1.z, b1.w));
        ((uint4*)kh)[i] = p;
    }
}

// ---------------------------------------------------------------------------
// Kernel T: K^T fp16 (g_KTh[b][d][k] = rne(K[b][k][d]))
// ---------------------------------------------------------------------------
__global__ __launch_bounds__(256)
void kT_transpose(const float* __restrict__ Kf, __half* __restrict__ KT)
{
    __shared__ float t[32][33];
    const int b  = blockIdx.z;
    const int k0 = blockIdx.x * 32;
    const int d0 = blockIdx.y * 32;
    const int tx = threadIdx.x, ty = threadIdx.y;
    const float* Kb = Kf + (size_t)b * LK_ * HID_;
#pragma unroll
    for (int j = 0; j < 32; j += 8)
        t[ty + j][tx] = Kb[(size_t)(k0 + ty + j) * HID_ + d0 + tx];
    __syncthreads();
    __half* KTb = KT + (size_t)b * HID_ * LK_;
#pragma unroll
    for (int j = 0; j < 32; j += 8)
        KTb[(size_t)(d0 + ty + j) * LK_ + k0 + tx] = __float2half_rn(t[tx][ty + j]);
}

// ---------------------------------------------------------------------------
// Shared GEMM skeleton: CTA 128x128, 4 warps (2Mx2N), warp tile 64x64,
// fp16 m16n8k16, 32 k-elems per stage, 4-stage cp.async ring.
// ---------------------------------------------------------------------------

// ---------------------------------------------------------------------------
// Kernel 1: g_Ath = fp16( exp( (Qh.Kh^T / 32) * mask ) )   (UNNORMALIZED)
// ---------------------------------------------------------------------------
__global__ __launch_bounds__(128, 2)
void k1_qk_exp(const __half* __restrict__ Q, const __half* __restrict__ Kf,
               const float* __restrict__ mask, __half* __restrict__ At)
{
    extern __shared__ unsigned sm[];
    unsigned* sA[4] = { sm, sm + 2560, sm + 2 * 2560, sm + 3 * 2560 };
    unsigned* sB[4] = { sm + 4 * 2560, sm + 5 * 2560, sm + 6 * 2560, sm + 7 * 2560 };

    const int b  = blockIdx.z;
    const int m0 = blockIdx.y * 128;
    const int n0 = blockIdx.x * 128;

    const __half* Qb = Q  + (size_t)b * LQ_ * HID_;
    const __half* Kb = Kf + (size_t)b * LK_ * HID_;

    const int tid  = threadIdx.x;
    const int wid  = tid >> 5;
    const int lane = tid & 31;
    const int qid  = lane >> 2;
    const int rid  = lane & 3;
    const int wm   = (wid & 1) * 64;
    const int wn   = (wid >> 1) * 64;

    const int lrow = tid >> 2;          // 0..31
    const int lch  = tid & 3;           // 16B chunk (8 halfs)

    uint32_t sAa[4], sBa[4];
#pragma unroll
    for (int u = 0; u < 4; u++) {
        sAa[u] = (uint32_t)__cvta_generic_to_shared(sA[u]);
        sBa[u] = (uint32_t)__cvta_generic_to_shared(sB[u]);
    }

    float acc[4][8][4];
#pragma unroll
    for (int i = 0; i < 4; i++)
#pragma unroll
        for (int j = 0; j < 8; j++)
#pragma unroll
            for (int c = 0; c < 4; c++) acc[i][j][c] = 0.0f;

    auto fill = [&](int stage, int buf) {
        const int kk = stage * 32;      // halfs
#pragma unroll
        for (int j = 0; j < 4; j++) {
            const int row = lrow + j * 32;
            cp_async16(sAa[buf] + (row * SKH + lch * 4) * 4,
                       Qb + (size_t)(m0 + row) * HID_ + kk + lch * 8);
            cp_async16(sBa[buf] + (row * SKH + lch * 4) * 4,
                       Kb + (size_t)(n0 + row) * HID_ + kk + lch * 8);
        }
    };

    fill(0, 0); CP_COMMIT();
    fill(1, 1); CP_COMMIT();
    fill(2, 2); CP_COMMIT();

    const int NIT = HID_ / 32;
    int cur = 0;
    for (int it = 0; it < NIT; it++) {
        CP_WAIT2();
        __syncthreads();
        if (it + 3 < NIT) fill(it + 3, (it + 3) & 3);
        CP_COMMIT();
        const unsigned* cA = sA[cur];
        const unsigned* cB = sB[cur];
        cur = (cur + 1) & 3;

#pragma unroll
        for (int h = 0; h < 2; h++) {
            const int ko = h * 8;       // half2 offset of this k16 step
            unsigned af[4][4];
#pragma unroll
            for (int mt = 0; mt < 4; mt++) {
                const int r = wm + mt * 16 + qid;
                af[mt][0] = cA[r * SKH + ko + rid];
                af[mt][1] = cA[(r + 8) * SKH + ko + rid];
                af[mt][2] = cA[r * SKH + ko + rid + 4];
                af[mt][3] = cA[(r + 8) * SKH + ko + rid + 4];
            }
            unsigned bf[8][2];
#pragma unroll
            for (int nt = 0; nt < 8; nt++) {
                const int c = wn + nt * 8 + qid;
                bf[nt][0] = cB[c * SKH + ko + rid];
                bf[nt][1] = cB[c * SKH + ko + rid + 4];
            }
#pragma unroll
            for (int mt = 0; mt < 4; mt++)
#pragma unroll
                for (int nt = 0; nt < 8; nt++)
                    mma_f16(acc[mt][nt], af[mt], bf[nt]);
        }
    }

    // epilogue: scale, mask-multiply, exp, fp16(rne), store unnormalized bits
    const float s = 0.03125f;
#pragma unroll
    for (int mt = 0; mt < 4; mt++) {
#pragma unroll
        for (int nt = 0; nt < 8; nt++) {
            const int r = m0 + wm + mt * 16 + qid;
            const int c = n0 + wn + nt * 8 + 2 * rid;
            const size_t i0 = ((size_t)b * LQ_ + r) * LK_ + c;
            const size_t i1 = ((size_t)b * LQ_ + r + 8) * LK_ + c;
            float2 ma = *(const float2*)(mask + i0);
            float2 mb = *(const float2*)(mask + i1);
            __half2 o0 = __floats2half2_rn(__expf(acc[mt][nt][0] * s * ma.x),
                                           __expf(acc[mt][nt][1] * s * ma.y));
            __half2 o1 = __floats2half2_rn(__expf(acc[mt][nt][2] * s * mb.x),
                                           __expf(acc[mt][nt][3] * s * mb.y));
            *(unsigned*)(At + i0) = h2u(o0);
            *(unsigned*)(At + i1) = h2u(o1);
        }
    }
}

// ---------------------------------------------------------------------------
// Kernel 2: read unnormalized fp16 P; row sum; write normalized f32 attn
// and invS[row].
// ---------------------------------------------------------------------------
__global__ __launch_bounds__(256)
void k2_norm(const __half* __restrict__ At, float* __restrict__ attn,
             float* __restrict__ invS)
{
    __shared__ float red[256];
    const __half* arow = At   + (size_t)blockIdx.x * LK_;
    float*        orow = attn + (size_t)blockIdx.x * LK_;
    const int tid = threadIdx.x;

    uint4 u = ((const uint4*)arow)[tid];      // 8 halfs
    float2 f0 = __half22float2(*(__half2*)&u.x);
    float2 f1 = __half22float2(*(__half2*)&u.y);
    float2 f2 = __half22float2(*(__half2*)&u.z);
    float2 f3 = __half22float2(*(__half2*)&u.w);
    float s = f0.x + f0.y + f1.x + f1.y + f2.x + f2.y + f3.x + f3.y;
    red[tid] = s;
    __syncthreads();
#pragma unroll
    for (int off = 128; off > 0; off >>= 1) {
        if (tid < off) red[tid] += red[tid + off];
        __syncthreads();
    }
    const float inv = 1.0f / red[0];
    ((float4*)orow)[2 * tid]     = make_float4(f0.x * inv, f0.y * inv, f1.x * inv, f1.y * inv);
    ((float4*)orow)[2 * tid + 1] = make_float4(f2.x * inv, f2.y * inv, f3.x * inv, f3.y * inv);
    if (tid == 0) invS[blockIdx.x] = inv;
}

// ---------------------------------------------------------------------------
// Kernel 3: context = (invS * Ath) . KTh^T  — both operands k-major fp16.
// ---------------------------------------------------------------------------
__global__ __launch_bounds__(128, 2)
void k3_av(const __half* __restrict__ A, const __half* __restrict__ KT,
           const float* __restrict__ invS, float* __restrict__ C)
{
    extern __shared__ unsigned sm[];
    unsigned* sA[4] = { sm, sm + 2560, sm + 2 * 2560, sm + 3 * 2560 };
    unsigned* sB[4] = { sm + 4 * 2560, sm + 5 * 2560, sm + 6 * 2560, sm + 7 * 2560 };

    const int b  = blockIdx.z;
    const int m0 = blockIdx.y * 128;
    const int n0 = blockIdx.x * 128;

    const __half* Ab = A  + (size_t)b * LQ_ * LK_;
    const __half* Kb = KT + (size_t)b * HID_ * LK_;

    const int tid  = threadIdx.x;
    const int wid  = tid >> 5;
    const int lane = tid & 31;
    const int qid  = lane >> 2;
    const int rid  = lane & 3;
    const int wm   = (wid & 1) * 64;
    const int wn   = (wid >> 1) * 64;

    const int lrow = tid >> 2;
    const int lch  = tid & 3;

    uint32_t sAa[4], sBa[4];
#pragma unroll
    for (int u = 0; u < 4; u++) {
        sAa[u] = (uint32_t)__cvta_generic_to_shared(sA[u]);
        sBa[u] = (uint32_t)__cvta_generic_to_shared(sB[u]);
    }

    float acc[4][8][4];
#pragma unroll
    for (int i = 0; i < 4; i++)
#pragma unroll
        for (int j = 0; j < 8; j++)
#pragma unroll
            for (int c = 0; c < 4; c++) acc[i][j][c] = 0.0f;

    auto fill = [&](int stage, int buf) {
        const int kk = stage * 32;
#pragma unroll
        for (int j = 0; j < 4; j++) {
            const int row = lrow + j * 32;
            cp_async16(sAa[buf] + (row * SKH + lch * 4) * 4,
                       Ab + (size_t)(m0 + row) * LK_ + kk + lch * 8);
            cp_async16(sBa[buf] + (row * SKH + lch * 4) * 4,
                       Kb + (size_t)(n0 + row) * LK_ + kk + lch * 8);
        }
    };

    fill(0, 0); CP_COMMIT();
    fill(1, 1); CP_COMMIT();
    fill(2, 2); CP_COMMIT();

    const int NIT = LK_ / 32;
    int cur = 0;
    for (int it = 0; it < NIT; it++) {
        CP_WAIT2();
        __syncthreads();
        if (it + 3 < NIT) fill(it + 3, (it + 3) & 3);
        CP_COMMIT();
        const unsigned* cA = sA[cur];
        const unsigned* cB = sB[cur];
        cur = (cur + 1) & 3;

#pragma unroll
        for (int h = 0; h < 2; h++) {
            const int ko = h * 8;
            unsigned af[4][4];
#pragma unroll
            for (int mt = 0; mt < 4; mt++) {
                const int r = wm + mt * 16 + qid;
                af[mt][0] = cA[r * SKH + ko + rid];
                af[mt][1] = cA[(r + 8) * SKH + ko + rid];
                af[mt][2] = cA[r * SKH + ko + rid + 4];
                af[mt][3] = cA[(r + 8) * SKH + ko + rid + 4];
            }
            unsigned bf[8][2];
#pragma unroll
            for (int nt = 0; nt < 8; nt++) {
                const int c = wn + nt * 8 + qid;
                bf[nt][0] = cB[c * SKH + ko + rid];
                bf[nt][1] = cB[c * SKH + ko + rid + 4];
            }
#pragma unroll
            for (int mt = 0; mt < 4; mt++)
#pragma unroll
                for (int nt = 0; nt < 8; nt++)
                    mma_f16(acc[mt][nt], af[mt], bf[nt]);
        }
    }

    // epilogue: scale by invS[row], store f32
#pragma unroll
    for (int mt = 0; mt < 4; mt++) {
        const int r  = m0 + wm + mt * 16 + qid;
        const float is0 = invS[(size_t)b * LQ_ + r];
        const float is1 = invS[(size_t)b * LQ_ + r + 8];
#pragma unroll
        for (int nt = 0; nt < 8; nt++) {
            const int c = n0 + wn + nt * 8 + 2 * rid;
            const size_t i0 = ((size_t)b * LQ_ + r) * HID_ + c;
            const size_t i1 = ((size_t)b * LQ_ + r + 8) * HID_ + c;
            *(float2*)(C + i0) = make_float2(acc[mt][nt][0] * is0, acc[mt][nt][1] * is0);
            *(float2*)(C + i1) = make_float2(acc[mt][nt][2] * is1, acc[mt][nt][3] * is1);
        }
    }
}

// ---------------------------------------------------------------------------
extern "C" void kernel_launch(void* const* d_in, const int* in_sizes, int n_in,
                              void* d_out, int out_size)
{
    const float* Q    = (const float*)d_in[0];
    const float* Kf   = (const float*)d_in[1];
    const float* mask = (const float*)d_in[2];

    float* ctx  = (float*)d_out;                      // [B, LQ, HID]
    float* attn = ctx + (size_t)B_ * LQ_ * HID_;      // [B, LQ, LK]

    void *qh = 0, *kh = 0, *kth = 0, *ath = 0, *sv = 0;
    cudaGetSymbolAddress(&qh,  g_Qh);
    cudaGetSymbolAddress(&kh,  g_Kh);
    cudaGetSymbolAddress(&kth, g_KTh);
    cudaGetSymbolAddress(&ath, g_Ath);
    cudaGetSymbolAddress(&sv,  g_S);

    const int smem = 8 * 2560 * 4;                    // 81920 B (both GEMMs)

    static bool attr_set = false;
    if (!attr_set) {
        cudaFuncSetAttribute(k1_qk_exp, cudaFuncAttributeMaxDynamicSharedMemorySize, smem);
        cudaFuncSetAttribute(k3_av,     cudaFuncAttributeMaxDynamicSharedMemorySize, smem);
        attr_set = true;
    }

    const int n8 = (B_ * LQ_ * HID_) / 8;
    k0_round<<<(n8 + 255) / 256, 256>>>(Q, Kf, (__half*)qh, (__half*)kh, n8);

    {
        dim3 g(LK_ / 32, HID_ / 32, B_);
        kT_transpose<<<g, dim3(32, 8)>>>(Kf, (__half*)kth);
    }

    dim3 g1(LK_ / 128, LQ_ / 128, B_);
    k1_qk_exp<<<g1, 128, smem>>>((const __half*)qh, (const __half*)kh, mask,
                                 (__half*)ath);

    k2_norm<<<B_ * LQ_, 256>>>((const __half*)ath, attn, (float*)sv);

    dim3 g3(HID_ / 128, LQ_ / 128, B_);
    k3_av<<<g3, 128, smem>>>((const __half*)ath, (const __half*)kth,
                             (const float*)sv, ctx);
}

// round 17
// speedup vs baseline: 2.3546x; 1.2724x over previous
#include <cuda_runtime.h>
#include <cuda_fp16.h>
#include <math.h>
#include <stdint.h>

#define B_   8
#define LQ_  2048
#define LK_  2048
#define HID_ 1024

// smem stride in half2 units: row = 20 half2 (80B). ldmatrix phases hit all
// 32 banks exactly once (20*row mod 32 spans {0,20,8,28,16,4,24,12} x 4 words).
#define SKH 20

// fp16 scratch (rne applied once; GEMMs load raw halfs)
__device__ __half g_Qh [(size_t)B_ * LQ_ * HID_];   // Q fp16, k-major
__device__ __half g_Kh [(size_t)B_ * LK_ * HID_];   // K fp16, k-major (for k1)
__device__ __half g_KTh[(size_t)B_ * HID_ * LK_];   // K^T fp16 (for k3)
__device__ __half g_Ath[(size_t)B_ * LQ_ * LK_];    // UNNORMALIZED exp(P), fp16
__device__ float  g_S  [(size_t)B_ * LQ_];          // per-row 1/sum

__device__ __forceinline__ unsigned h2u(__half2 h) {
    return *(unsigned*)&h;
}

__device__ __forceinline__ void mma_f16(float* d, const unsigned* a, const unsigned* b) {
    asm volatile(
        "mma.sync.aligned.m16n8k16.row.col.f32.f16.f16.f32 "
        "{%0,%1,%2,%3}, {%4,%5,%6,%7}, {%8,%9}, {%0,%1,%2,%3};\n"
        : "+f"(d[0]), "+f"(d[1]), "+f"(d[2]), "+f"(d[3])
        : "r"(a[0]), "r"(a[1]), "r"(a[2]), "r"(a[3]),
          "r"(b[0]), "r"(b[1]));
}

__device__ __forceinline__ void ldsm_x4(unsigned& r0, unsigned& r1,
                                        unsigned& r2, unsigned& r3, uint32_t addr) {
    asm volatile("ldmatrix.sync.aligned.m8n8.x4.shared.b16 {%0,%1,%2,%3}, [%4];"
                 : "=r"(r0), "=r"(r1), "=r"(r2), "=r"(r3) : "r"(addr));
}

__device__ __forceinline__ void cp_async16(uint32_t smem_addr, const void* gptr) {
    asm volatile("cp.async.cg.shared.global [%0], [%1], 16;"
                 :: "r"(smem_addr), "l"(gptr));
}
#define CP_COMMIT() asm volatile("cp.async.commit_group;" ::: "memory")
#define CP_WAIT2()  asm volatile("cp.async.wait_group 2;" ::: "memory")

// ---------------------------------------------------------------------------
// Kernel 0: f32 -> fp16 (rne) for Q and K, k-major (8 elems per thread)
// ---------------------------------------------------------------------------
__global__ __launch_bounds__(256)
void k0_round(const float* __restrict__ q, const float* __restrict__ k,
              __half* __restrict__ qh, __half* __restrict__ kh, int n8)
{
    const int i = blockIdx.x * 256 + threadIdx.x;
    if (i < n8) {
        float4 a0 = ((const float4*)q)[2 * i];
        float4 a1 = ((const float4*)q)[2 * i + 1];
        uint4 o;
        o.x = h2u(__floats2half2_rn(a0.x, a0.y));
        o.y = h2u(__floats2half2_rn(a0.z, a0.w));
        o.z = h2u(__floats2half2_rn(a1.x, a1.y));
        o.w = h2u(__floats2half2_rn(a1.z, a1.w));
        ((uint4*)qh)[i] = o;
        float4 b0 = ((const float4*)k)[2 * i];
        float4 b1 = ((const float4*)k)[2 * i + 1];
        uint4 p;
        p.x = h2u(__floats2half2_rn(b0.x, b0.y));
        p.y = h2u(__floats2half2_rn(b0.z, b0.w));
        p.z = h2u(__floats2half2_rn(b1.x, b1.y));
        p.w = h2u(__floats2half2_rn(b1.z, b1.w));
        ((uint4*)kh)[i] = p;
    }
}

// ---------------------------------------------------------------------------
// Kernel T: K^T fp16 (g_KTh[b][d][k] = rne(K[b][k][d]))
// ---------------------------------------------------------------------------
__global__ __launch_bounds__(256)
void kT_transpose(const float* __restrict__ Kf, __half* __restrict__ KT)
{
    __shared__ float t[32][33];
    const int b  = blockIdx.z;
    const int k0 = blockIdx.x * 32;
    const int d0 = blockIdx.y * 32;
    const int tx = threadIdx.x, ty = threadIdx.y;
    const float* Kb = Kf + (size_t)b * LK_ * HID_;
#pragma unroll
    for (int j = 0; j < 32; j += 8)
        t[ty + j][tx] = Kb[(size_t)(k0 + ty + j) * HID_ + d0 + tx];
    __syncthreads();
    __half* KTb = KT + (size_t)b * HID_ * LK_;
#pragma unroll
    for (int j = 0; j < 32; j += 8)
        KTb[(size_t)(d0 + ty + j) * LK_ + k0 + tx] = __float2half_rn(t[tx][ty + j]);
}

// ---------------------------------------------------------------------------
// Kernel 1: g_Ath = fp16( exp( (Qh.Kh^T / 32) * mask ) )   (UNNORMALIZED)
// CTA 128x128, 4 warps (2Mx2N), warp tile 64x64, fp16 m16n8k16,
// 4-stage cp.async ring, ldmatrix.x4 fragment loads.
// ---------------------------------------------------------------------------
__global__ __launch_bounds__(128, 2)
void k1_qk_exp(const __half* __restrict__ Q, const __half* __restrict__ Kf,
               const float* __restrict__ mask, __half* __restrict__ At)
{
    extern __shared__ unsigned sm[];

    const int b  = blockIdx.z;
    const int m0 = blockIdx.y * 128;
    const int n0 = blockIdx.x * 128;

    const __half* Qb = Q  + (size_t)b * LQ_ * HID_;
    const __half* Kb = Kf + (size_t)b * LK_ * HID_;

    const int tid  = threadIdx.x;
    const int wid  = tid >> 5;
    const int lane = tid & 31;
    const int qid  = lane >> 2;
    const int rid  = lane & 3;
    const int wm   = (wid & 1) * 64;
    const int wn   = (wid >> 1) * 64;

    const int lrow = tid >> 2;          // 0..31
    const int lch  = tid & 3;           // 16B chunk

    // ldmatrix per-lane address components (in half2 words)
    const int aRow = lane & 15;                 // row within 16-row block
    const int aCh  = (lane >> 4) * 4;           // k-chunk (half2) select
    const int bRow = lane & 7;                  // row within 8-row block
    const int bMs  = (lane >> 4);               // nt-pair half select
    const int bCh  = ((lane >> 3) & 1) * 4;     // k-chunk select

    uint32_t sAa[4], sBa[4];
#pragma unroll
    for (int u = 0; u < 4; u++) {
        sAa[u] = (uint32_t)__cvta_generic_to_shared(sm + u * 2560);
        sBa[u] = (uint32_t)__cvta_generic_to_shared(sm + (4 + u) * 2560);
    }

    float acc[4][8][4];
#pragma unroll
    for (int i = 0; i < 4; i++)
#pragma unroll
        for (int j = 0; j < 8; j++)
#pragma unroll
            for (int c = 0; c < 4; c++) acc[i][j][c] = 0.0f;

    auto fill = [&](int stage, int buf) {
        const int kk = stage * 32;      // halfs
#pragma unroll
        for (int j = 0; j < 4; j++) {
            const int row = lrow + j * 32;
            cp_async16(sAa[buf] + (row * SKH + lch * 4) * 4,
                       Qb + (size_t)(m0 + row) * HID_ + kk + lch * 8);
            cp_async16(sBa[buf] + (row * SKH + lch * 4) * 4,
                       Kb + (size_t)(n0 + row) * HID_ + kk + lch * 8);
        }
    };

    fill(0, 0); CP_COMMIT();
    fill(1, 1); CP_COMMIT();
    fill(2, 2); CP_COMMIT();

    const int NIT = HID_ / 32;
    int cur = 0;
    for (int it = 0; it < NIT; it++) {
        CP_WAIT2();
        __syncthreads();
        if (it + 3 < NIT) fill(it + 3, (it + 3) & 3);
        CP_COMMIT();
        const uint32_t aBase = sAa[cur];
        const uint32_t bBase = sBa[cur];
        cur = (cur + 1) & 3;

#pragma unroll
        for (int h = 0; h < 2; h++) {
            const int ko = h * 8;       // half2 offset of this k16 step
            unsigned af[4][4];
#pragma unroll
            for (int mt = 0; mt < 4; mt++)
                ldsm_x4(af[mt][0], af[mt][1], af[mt][2], af[mt][3],
                        aBase + ((wm + mt * 16 + aRow) * SKH + ko + aCh) * 4);
            unsigned bf[8][2];
#pragma unroll
            for (int p = 0; p < 4; p++)
                ldsm_x4(bf[2 * p][0], bf[2 * p][1], bf[2 * p + 1][0], bf[2 * p + 1][1],
                        bBase + ((wn + (2 * p + bMs) * 8 + bRow) * SKH + ko + bCh) * 4);
#pragma unroll
            for (int mt = 0; mt < 4; mt++)
#pragma unroll
                for (int nt = 0; nt < 8; nt++)
                    mma_f16(acc[mt][nt], af[mt], bf[nt]);
        }
    }

    // epilogue: scale, mask-multiply, exp, fp16(rne), store unnormalized bits
    const float s = 0.03125f;
#pragma unroll
    for (int mt = 0; mt < 4; mt++) {
#pragma unroll
        for (int nt = 0; nt < 8; nt++) {
            const int r = m0 + wm + mt * 16 + qid;
            const int c = n0 + wn + nt * 8 + 2 * rid;
            const size_t i0 = ((size_t)b * LQ_ + r) * LK_ + c;
            const size_t i1 = ((size_t)b * LQ_ + r + 8) * LK_ + c;
            float2 ma = *(const float2*)(mask + i0);
            float2 mb = *(const float2*)(mask + i1);
            __half2 o0 = __floats2half2_rn(__expf(acc[mt][nt][0] * s * ma.x),
                                           __expf(acc[mt][nt][1] * s * ma.y));
            __half2 o1 = __floats2half2_rn(__expf(acc[mt][nt][2] * s * mb.x),
                                           __expf(acc[mt][nt][3] * s * mb.y));
            *(unsigned*)(At + i0) = h2u(o0);
            *(unsigned*)(At + i1) = h2u(o1);
        }
    }
}

// ---------------------------------------------------------------------------
// Kernel 2: read unnormalized fp16 P; row sum; write normalized f32 attn
// and invS[row].
// ---------------------------------------------------------------------------
__global__ __launch_bounds__(256)
void k2_norm(const __half* __restrict__ At, float* __restrict__ attn,
             float* __restrict__ invS)
{
    __shared__ float red[256];
    const __half* arow = At   + (size_t)blockIdx.x * LK_;
    float*        orow = attn + (size_t)blockIdx.x * LK_;
    const int tid = threadIdx.x;

    uint4 u = ((const uint4*)arow)[tid];      // 8 halfs
    float2 f0 = __half22float2(*(__half2*)&u.x);
    float2 f1 = __half22float2(*(__half2*)&u.y);
    float2 f2 = __half22float2(*(__half2*)&u.z);
    float2 f3 = __half22float2(*(__half2*)&u.w);
    float s = f0.x + f0.y + f1.x + f1.y + f2.x + f2.y + f3.x + f3.y;
    red[tid] = s;
    __syncthreads();
#pragma unroll
    for (int off = 128; off > 0; off >>= 1) {
        if (tid < off) red[tid] += red[tid + off];
        __syncthreads();
    }
    const float inv = 1.0f / red[0];
    ((float4*)orow)[2 * tid]     = make_float4(f0.x * inv, f0.y * inv, f1.x * inv, f1.y * inv);
    ((float4*)orow)[2 * tid + 1] = make_float4(f2.x * inv, f2.y * inv, f3.x * inv, f3.y * inv);
    if (tid == 0) invS[blockIdx.x] = inv;
}

// ---------------------------------------------------------------------------
// Kernel 3: context = (invS * Ath) . KTh^T  — both operands k-major fp16.
// Same skeleton + ldmatrix fragments.
// ---------------------------------------------------------------------------
__global__ __launch_bounds__(128, 2)
void k3_av(const __half* __restrict__ A, const __half* __restrict__ KT,
           const float* __restrict__ invS, float* __restrict__ C)
{
    extern __shared__ unsigned sm[];

    const int b  = blockIdx.z;
    const int m0 = blockIdx.y * 128;
    const int n0 = blockIdx.x * 128;

    const __half* Ab = A  + (size_t)b * LQ_ * LK_;
    const __half* Kb = KT + (size_t)b * HID_ * LK_;

    const int tid  = threadIdx.x;
    const int wid  = tid >> 5;
    const int lane = tid & 31;
    const int qid  = lane >> 2;
    const int rid  = lane & 3;
    const int wm   = (wid & 1) * 64;
    const int wn   = (wid >> 1) * 64;

    const int lrow = tid >> 2;
    const int lch  = tid & 3;

    const int aRow = lane & 15;
    const int aCh  = (lane >> 4) * 4;
    const int bRow = lane & 7;
    const int bMs  = (lane >> 4);
    const int bCh  = ((lane >> 3) & 1) * 4;

    uint32_t sAa[4], sBa[4];
#pragma unroll
    for (int u = 0; u < 4; u++) {
        sAa[u] = (uint32_t)__cvta_generic_to_shared(sm + u * 2560);
        sBa[u] = (uint32_t)__cvta_generic_to_shared(sm + (4 + u) * 2560);
    }

    float acc[4][8][4];
#pragma unroll
    for (int i = 0; i < 4; i++)
#pragma unroll
        for (int j = 0; j < 8; j++)
#pragma unroll
            for (int c = 0; c < 4; c++) acc[i][j][c] = 0.0f;

    auto fill = [&](int stage, int buf) {
        const int kk = stage * 32;
#pragma unroll
        for (int j = 0; j < 4; j++) {
            const int row = lrow + j * 32;
            cp_async16(sAa[buf] + (row * SKH + lch * 4) * 4,
                       Ab + (size_t)(m0 + row) * LK_ + kk + lch * 8);
            cp_async16(sBa[buf] + (row * SKH + lch * 4) * 4,
                       Kb + (size_t)(n0 + row) * LK_ + kk + lch * 8);
        }
    };

    fill(0, 0); CP_COMMIT();
    fill(1, 1); CP_COMMIT();
    fill(2, 2); CP_COMMIT();

    const int NIT = LK_ / 32;
    int cur = 0;
    for (int it = 0; it < NIT; it++) {
        CP_WAIT2();
        __syncthreads();
        if (it + 3 < NIT) fill(it + 3, (it + 3) & 3);
        CP_COMMIT();
        const uint32_t aBase = sAa[cur];
        const uint32_t bBase = sBa[cur];
        cur = (cur + 1) & 3;

#pragma unroll
        for (int h = 0; h < 2; h++) {
            const int ko = h * 8;
            unsigned af[4][4];
#pragma unroll
            for (int mt = 0; mt < 4; mt++)
                ldsm_x4(af[mt][0], af[mt][1], af[mt][2], af[mt][3],
                        aBase + ((wm + mt * 16 + aRow) * SKH + ko + aCh) * 4);
            unsigned bf[8][2];
#pragma unroll
            for (int p = 0; p < 4; p++)
                ldsm_x4(bf[2 * p][0], bf[2 * p][1], bf[2 * p + 1][0], bf[2 * p + 1][1],
                        bBase + ((wn + (2 * p + bMs) * 8 + bRow) * SKH + ko + bCh) * 4);
#pragma unroll
            for (int mt = 0; mt < 4; mt++)
#pragma unroll
                for (int nt = 0; nt < 8; nt++)
                    mma_f16(acc[mt][nt], af[mt], bf[nt]);
        }
    }

    // epilogue: scale by invS[row], store f32
#pragma unroll
    for (int mt = 0; mt < 4; mt++) {
        const int r  = m0 + wm + mt * 16 + qid;
        const float is0 = invS[(size_t)b * LQ_ + r];
        const float is1 = invS[(size_t)b * LQ_ + r + 8];
#pragma unroll
        for (int nt = 0; nt < 8; nt++) {
            const int c = n0 + wn + nt * 8 + 2 * rid;
            const size_t i0 = ((size_t)b * LQ_ + r) * HID_ + c;
            const size_t i1 = ((size_t)b * LQ_ + r + 8) * HID_ + c;
            *(float2*)(C + i0) = make_float2(acc[mt][nt][0] * is0, acc[mt][nt][1] * is0);
            *(float2*)(C + i1) = make_float2(acc[mt][nt][2] * is1, acc[mt][nt][3] * is1);
        }
    }
}

// ---------------------------------------------------------------------------
extern "C" void kernel_launch(void* const* d_in, const int* in_sizes, int n_in,
                              void* d_out, int out_size)
{
    const float* Q    = (const float*)d_in[0];
    const float* Kf   = (const float*)d_in[1];
    const float* mask = (const float*)d_in[2];

    float* ctx  = (float*)d_out;                      // [B, LQ, HID]
    float* attn = ctx + (size_t)B_ * LQ_ * HID_;      // [B, LQ, LK]

    void *qh = 0, *kh = 0, *kth = 0, *ath = 0, *sv = 0;
    cudaGetSymbolAddress(&qh,  g_Qh);
    cudaGetSymbolAddress(&kh,  g_Kh);
    cudaGetSymbolAddress(&kth, g_KTh);
    cudaGetSymbolAddress(&ath, g_Ath);
    cudaGetSymbolAddress(&sv,  g_S);

    const int smem = 8 * 2560 * 4;                    // 81920 B (both GEMMs)

    static bool attr_set = false;
    if (!attr_set) {
        cudaFuncSetAttribute(k1_qk_exp, cudaFuncAttributeMaxDynamicSharedMemorySize, smem);
        cudaFuncSetAttribute(k3_av,     cudaFuncAttributeMaxDynamicSharedMemorySize, smem);
        attr_set = true;
    }

    const int n8 = (B_ * LQ_ * HID_) / 8;
    k0_round<<<(n8 + 255) / 256, 256>>>(Q, Kf, (__half*)qh, (__half*)kh, n8);

    {
        dim3 g(LK_ / 32, HID_ / 32, B_);
        kT_transpose<<<g, dim3(32, 8)>>>(Kf, (__half*)kth);
    }

    dim3 g1(LK_ / 128, LQ_ / 128, B_);
    k1_qk_exp<<<g1, 128, smem>>>((const __half*)qh, (const __half*)kh, mask,
                                 (__half*)ath);

    k2_norm<<<B_ * LQ_, 256>>>((const __half*)ath, attn, (float*)sv);

    dim3 g3(HID_ / 128, LQ_ / 128, B_);
    k3_av<<<g3, 128, smem>>>((const __half*)ath, (const __half*)kth,
                             (const float*)sv, ctx);
}